// round 1
// baseline (speedup 1.0000x reference)
#include <cuda_runtime.h>
#include <cuda_bf16.h>

// Direct conv2d, fp32, stride 1, pad 1.
// x: [32,128,56,56], W: [256,128,3,3] -> out: [32,256,56,56]
//
// Strategy: register-tiled direct conv using packed fma.rn.f32x2 (FFMA2).
// Block = 256 threads computes TILE_OC=128 output channels x (8 x 14) pixels.
// Thread = 8 oc (4 f32x2 pairs, packed over oc) x 7 px = 28 f32x2 accumulators.

#define CI       8
#define TILE_OC  128
#define TILE_H   8
#define TILE_W   14

#define N_IMG    32
#define C_IN     128
#define HW       56
#define OC_TOT   256
#define KWTS     1152           // 128*3*3 per output channel

typedef unsigned long long ull;

__device__ __forceinline__ void ffma2(ull& d, ull a, ull b) {
    asm("fma.rn.f32x2 %0, %1, %2, %0;" : "+l"(d) : "l"(a), "l"(b));
}
__device__ __forceinline__ ull dup2(float v) {
    ull r;
    asm("mov.b64 %0, {%1, %2};" : "=l"(r) : "f"(v), "f"(v));
    return r;
}
__device__ __forceinline__ float2 unpack2(ull v) {
    float2 r;
    asm("mov.b64 {%0, %1}, %2;" : "=f"(r.x), "=f"(r.y) : "l"(v));
    return r;
}

__global__ __launch_bounds__(256, 2)
void conv_ffma2_kernel(const float* __restrict__ x,
                       const float* __restrict__ w,
                       float* __restrict__ out)
{
    // x tile: [ci][row 0..9][col 0..15], row stride 20 -> conflict-free LDS.32
    __shared__ float s_x[CI][TILE_H + 2][20];
    // w tile: [ci*9+rs][oc], row stride 130 (even -> 8B-aligned pairs,
    // <=2-way STS transpose conflict, contiguous oc -> LDS.64 pairs)
    __shared__ __align__(16) float s_w[CI * 9][130];

    const int tid  = threadIdx.x;
    const int oc_t = tid >> 4;        // 0..15 -> owns oc_t*8 .. oc_t*8+7
    const int pg   = tid & 15;        // 16 pixel groups
    const int r    = pg >> 1;         // tile row 0..7
    const int cb   = (pg & 1) * 7;    // tile col base {0,7}

    const int n      = blockIdx.z >> 1;
    const int ocBase = (blockIdx.z & 1) * TILE_OC;
    const int hBase  = blockIdx.y * TILE_H;
    const int wBase  = blockIdx.x * TILE_W;

    ull acc[4][7];
#pragma unroll
    for (int p = 0; p < 4; p++)
#pragma unroll
        for (int j = 0; j < 7; j++) acc[p][j] = 0ull;

    const float* xn = x + (size_t)n * C_IN * HW * HW;

    for (int cc = 0; cc < C_IN; cc += CI) {
        __syncthreads();   // protect previous iteration's reads

        // ---- stage x tile: CI x 10 x 16 = 1280 elems (5 per thread) ----
#pragma unroll
        for (int t = 0; t < 5; t++) {
            int idx = tid + t * 256;           // 0..1279
            int ci  = idx / 160;               // 10*16 per channel
            int rem = idx - ci * 160;
            int row = rem >> 4;
            int col = rem & 15;
            int hh  = hBase + row - 1;
            int ww  = wBase + col - 1;
            float v = 0.f;
            if ((unsigned)hh < (unsigned)HW && (unsigned)ww < (unsigned)HW)
                v = xn[((cc + ci) * HW + hh) * HW + ww];
            s_x[ci][row][col] = v;
        }

        // ---- stage w tile: 128 oc x 72 crs = 9216 elems (36 per thread) ----
        // lanes -> consecutive crs within one oc row (coalesced LDG)
#pragma unroll
        for (int t = 0; t < 36; t++) {
            int idx = tid + t * 256;           // 0..9215
            int o   = idx / 72;                // 0..127
            int crs = idx - o * 72;            // ci*9 + rs, contiguous in W
            s_w[crs][o] = w[(ocBase + o) * KWTS + cc * 9 + crs];
        }
        __syncthreads();

        // ---- compute ----
#pragma unroll 1
        for (int ci = 0; ci < CI; ci++) {
#pragma unroll
            for (int dr = 0; dr < 3; dr++) {
                // x window: cols cb..cb+8, duplicated into f32x2 lanes
                ull xw[9];
                const float* xrow = &s_x[ci][r + dr][cb];
#pragma unroll
                for (int j = 0; j < 9; j++) xw[j] = dup2(xrow[j]);

#pragma unroll
                for (int dc = 0; dc < 3; dc++) {
                    const float* wrow = &s_w[ci * 9 + dr * 3 + dc][oc_t * 8];
#pragma unroll
                    for (int p = 0; p < 4; p++) {
                        const ull wv = *(const ull*)(wrow + p * 2);  // {w_oc, w_oc+1}
#pragma unroll
                        for (int j = 0; j < 7; j++)
                            ffma2(acc[p][j], wv, xw[j + dc]);
                    }
                }
            }
        }
    }

    // ---- epilogue ----
    float* outn = out + (size_t)n * OC_TOT * HW * HW;
    const int oh = hBase + r;
#pragma unroll
    for (int p = 0; p < 4; p++) {
        int oc0 = ocBase + oc_t * 8 + p * 2;
        float* o0 = outn + (oc0 * HW + oh) * HW + wBase + cb;
        float* o1 = o0 + HW * HW;   // oc0+1
#pragma unroll
        for (int j = 0; j < 7; j++) {
            float2 v = unpack2(acc[p][j]);
            o0[j] = v.x;
            o1[j] = v.y;
        }
    }
}

extern "C" void kernel_launch(void* const* d_in, const int* in_sizes, int n_in,
                              void* d_out, int out_size)
{
    const float* x = (const float*)d_in[0];
    const float* w = (const float*)d_in[1];
    float* out     = (float*)d_out;

    dim3 grid(HW / TILE_W, HW / TILE_H, N_IMG * (OC_TOT / TILE_OC)); // (4,7,64)
    conv_ffma2_kernel<<<grid, 256>>>(x, w, out);
}

// round 6
// speedup vs baseline: 1.9826x; 1.9826x over previous
#include <cuda_runtime.h>
#include <cstdint>

// Implicit-GEMM conv2d via legacy mma.sync tf32 (sm_80+ PTX).
// x: [32,128,56,56] f32, W: [256,128,3,3] f32 -> out: [32,256,56,56] f32
// GEMM: D[oc, pix] = W[oc, K] * im2col(x)[K, pix],  K = 128*9 = 1152.
// CTA tile: 128 oc x 128 pix. Warp grid 2(M) x 4(N), warp tile 64x32.
// KC=16 k-chunks, double-buffered in 40KB STATIC shared memory:
// no dynamic smem, no cudaFuncSetAttribute (the harness's device-limit
// guard killed every prior run that called it).

#define NIMG   32
#define CIN    128
#define HWDIM  56
#define OCTOT  256
#define IMGPIX 3136
#define XCH    (CIN*IMGPIX)
#define KTOT   1152
#define NPIX   (NIMG*IMGPIX)
#define KC     16
#define NSTEP  (KTOT/KC)      // 72
#define TILE_N 128
#define LDT    20             // smem row stride (floats): fragment-conflict-free
#define TSZ    (128*LDT)      // 2560 elems per tile buffer

__device__ __forceinline__ uint32_t cvt_tf32(float f) {
    uint32_t r;
    asm("cvt.rna.tf32.f32 %0, %1;" : "=r"(r) : "f"(f));
    return r;
}

__device__ __forceinline__ void mma8(float* c, const uint32_t* a, const uint32_t* b) {
    asm volatile(
        "mma.sync.aligned.m16n8k8.row.col.f32.tf32.tf32.f32 "
        "{%0,%1,%2,%3}, {%4,%5,%6,%7}, {%8,%9}, {%0,%1,%2,%3};"
        : "+f"(c[0]), "+f"(c[1]), "+f"(c[2]), "+f"(c[3])
        : "r"(a[0]), "r"(a[1]), "r"(a[2]), "r"(a[3]), "r"(b[0]), "r"(b[1]));
}

__global__ __launch_bounds__(256, 2)
void conv_mma_kernel(const float* __restrict__ x, const float* __restrict__ w,
                     float* __restrict__ out)
{
    __shared__ uint32_t smem[4 * TSZ];            // A0 A1 B0 B1 = 40 KB
    uint32_t* const As0 = smem;
    uint32_t* const As1 = smem + TSZ;
    uint32_t* const Bs0 = smem + 2 * TSZ;
    uint32_t* const Bs1 = smem + 3 * TSZ;

    const int tid  = threadIdx.x;
    const int lane = tid & 31;
    const int warp = tid >> 5;
    const int wm   = warp >> 2;                   // 0..1 (M)
    const int wn   = warp & 3;                    // 0..3 (N)
    const int g    = lane >> 2;                   // groupID 0..7
    const int tig  = lane & 3;                    // thread-in-group 0..3

    const int tileBase = blockIdx.x * TILE_N;
    const int ocBase   = blockIdx.y * 128;

    // B-load mapping: thread -> (local pixel, k-half of 8)
    const int pl = tid & 127;
    const int kh = tid >> 7;                      // 0/1 -> k offset 8*kh
    const int P  = tileBase + pl;
    const int n_img = P / IMGPIX;
    const int q  = P - n_img * IMGPIX;
    const int hh = q / HWDIM;
    const int ww = q - hh * HWDIM;
    const float* xb = x + (size_t)n_img * XCH + hh * HWDIM + ww;

    float acc[4][4][4];
#pragma unroll
    for (int i = 0; i < 4; i++)
#pragma unroll
        for (int j = 0; j < 4; j++)
#pragma unroll
            for (int k2 = 0; k2 < 4; k2++) acc[i][j][k2] = 0.f;

    // ---- stage loader ----
    auto load_stage = [&](uint32_t* Ad, uint32_t* Bd, int cc) {
        // A: 128 oc x 16 k = 512 float4 loads, coalesced
#pragma unroll
        for (int i = 0; i < 2; i++) {
            int item = i * 256 + tid;             // 0..511
            int oc = item >> 2;
            int kq = item & 3;
            float4 v = *(const float4*)(w + (size_t)(ocBase + oc) * KTOT + cc + kq * 4);
            uint32_t* dst = Ad + oc * LDT + kq * 4;
            dst[0] = cvt_tf32(v.x); dst[1] = cvt_tf32(v.y);
            dst[2] = cvt_tf32(v.z); dst[3] = cvt_tf32(v.w);
        }
        // B: im2col gather, 128 pix x 16 k; lanes = consecutive pixels (coalesced)
        uint32_t* brow = Bd + pl * LDT + kh * 8;
#pragma unroll
        for (int j = 0; j < 8; j++) {
            int k  = cc + kh * 8 + j;
            int ci = k / 9;
            int rs = k - ci * 9;
            int dr = rs / 3 - 1;
            int ds = rs - (rs / 3) * 3 - 1;
            bool in = ((unsigned)(hh + dr) < HWDIM) && ((unsigned)(ww + ds) < HWDIM);
            float f = in ? xb[ci * IMGPIX + dr * HWDIM + ds] : 0.f;
            brow[j] = cvt_tf32(f);
        }
    };

    load_stage(As0, Bs0, 0);
    __syncthreads();

    for (int s = 0; s < NSTEP; s++) {
        const int cur = s & 1;
        const uint32_t* A = cur ? As1 : As0;
        const uint32_t* B = cur ? Bs1 : Bs0;
        if (s + 1 < NSTEP)
            load_stage(cur ? As0 : As1, cur ? Bs0 : Bs1, (s + 1) * KC);

#pragma unroll
        for (int ks = 0; ks < 2; ks++) {
            uint32_t a[4][4], b[4][2];
#pragma unroll
            for (int mt = 0; mt < 4; mt++) {
                const uint32_t* ap = A + (wm * 64 + mt * 16 + g) * LDT + ks * 8 + tig;
                a[mt][0] = ap[0];
                a[mt][1] = ap[8 * LDT];
                a[mt][2] = ap[4];
                a[mt][3] = ap[8 * LDT + 4];
            }
#pragma unroll
            for (int nt = 0; nt < 4; nt++) {
                const uint32_t* bp = B + (wn * 32 + nt * 8 + g) * LDT + ks * 8 + tig;
                b[nt][0] = bp[0];
                b[nt][1] = bp[4];
            }
#pragma unroll
            for (int mt = 0; mt < 4; mt++)
#pragma unroll
                for (int nt = 0; nt < 4; nt++)
                    mma8(acc[mt][nt], a[mt], b[nt]);
        }
        __syncthreads();
    }

    // ---- epilogue: direct STG.64 (c0,c1 are adjacent pixels) ----
#pragma unroll
    for (int nt = 0; nt < 4; nt++) {
        int Pp = tileBase + wn * 32 + nt * 8 + 2 * tig;
        int n2 = Pp / IMGPIX;
        int rm = Pp - n2 * IMGPIX;
        float* baseo = out + ((size_t)n2 * OCTOT + ocBase) * IMGPIX + rm;
#pragma unroll
        for (int mt = 0; mt < 4; mt++) {
            int oc0 = wm * 64 + mt * 16 + g;
            float2 v0 = make_float2(acc[mt][nt][0], acc[mt][nt][1]);
            float2 v1 = make_float2(acc[mt][nt][2], acc[mt][nt][3]);
            *(float2*)(baseo + (size_t)oc0 * IMGPIX)       = v0;
            *(float2*)(baseo + (size_t)(oc0 + 8) * IMGPIX) = v1;
        }
    }
}

extern "C" void kernel_launch(void* const* d_in, const int* in_sizes, int n_in,
                              void* d_out, int out_size)
{
    const float* x = (const float*)d_in[0];
    const float* w = (const float*)d_in[1];
    float* out     = (float*)d_out;

    dim3 grid(NPIX / TILE_N, OCTOT / 128);         // (784, 2)
    conv_mma_kernel<<<grid, 256>>>(x, w, out);
}